// round 1
// baseline (speedup 1.0000x reference)
#include <cuda_runtime.h>
#include <cstdint>
#include <cstddef>

#define TPB   256
#define NKEY  127
#define NH    4
#define DK    64
#define DOUT  256
#define KVSTR 68   // padded kv row stride (floats): 16B-aligned, conflict-friendly

static constexpr int SMEM_FLOATS =
    NKEY * KVSTR   // s_kv
  + DOUT * DK      // s_wk
  + DOUT           // s_qb
  + DK             // s_q
  + DK             // s_ws
  + NH * 128       // s_sc
  + NH * 128       // s_w
  + DOUT;          // s_wv
static constexpr int SMEM_BYTES = SMEM_FLOATS * 4;

__device__ __forceinline__ float tanh_fast(float x) {
    float y;
    asm("tanh.approx.f32 %0, %1;" : "=f"(y) : "f"(x));
    return y;
}
__device__ __forceinline__ unsigned long long fma2(unsigned long long a,
                                                   unsigned long long b,
                                                   unsigned long long c) {
    unsigned long long d;
    asm("fma.rn.f32x2 %0, %1, %2, %3;" : "=l"(d) : "l"(a), "l"(b), "l"(c));
    return d;
}
__device__ __forceinline__ unsigned long long add2(unsigned long long a,
                                                   unsigned long long b) {
    unsigned long long d;
    asm("add.rn.f32x2 %0, %1, %2;" : "=l"(d) : "l"(a), "l"(b));
    return d;
}

__global__ void __launch_bounds__(TPB, 2)
raamh_kernel(const float* __restrict__ q_x, const float* __restrict__ kv_x,
             const float* __restrict__ Wk,  const float* __restrict__ Wq,
             const float* __restrict__ Wv,  const float* __restrict__ bias,
             const float* __restrict__ Ws,  const float* __restrict__ bs,
             float* __restrict__ out)
{
    extern __shared__ float smem[];
    float* s_kv = smem;                      // [127][68]
    float* s_wk = s_kv + NKEY * KVSTR;       // [256][64]
    float* s_qb = s_wk + DOUT * DK;          // [256]  q-proj + bias
    float* s_q  = s_qb + DOUT;               // [64]
    float* s_ws = s_q  + DK;                 // [64]
    float* s_sc = s_ws + DK;                 // [4][128] scores
    float* s_w  = s_sc + NH * 128;           // [4][128] softmax weights
    float* s_wv = s_w  + NH * 128;           // [4][64]  weighted kv

    const int tid = threadIdx.x;
    const int bt  = blockIdx.x;              // fused (b, t)
    const int h   = tid >> 6;                // head for this thread
    const int lg  = tid & 63;                // lane within head group

    // ---- stage kv tile (127x64, contiguous) into padded SMEM ----
    const float4* kvg = (const float4*)(kv_x + (size_t)bt * (NKEY * DK));
    #pragma unroll
    for (int j = tid; j < NKEY * DK / 4; j += TPB) {
        float4 v = kvg[j];
        int n = (4 * j) >> 6;
        int c = (4 * j) & 63;
        *(float4*)(s_kv + n * KVSTR + c) = v;
    }
    // ---- stage Wk (256x64) ----
    const float4* wkg = (const float4*)Wk;
    #pragma unroll
    for (int j = tid; j < DOUT * DK / 4; j += TPB)
        ((float4*)s_wk)[j] = wkg[j];
    if (tid < DK) {
        s_q[tid]  = q_x[bt * DK + tid];
        s_ws[tid] = Ws[tid];
    }
    __syncthreads();

    // ---- query projection + bias: qb[o] = q . Wq[o] + bias[o&63] ----
    {
        const float4* wq4 = (const float4*)(Wq + tid * DK);
        float a0 = 0.f, a1 = 0.f, a2 = 0.f, a3 = 0.f;
        #pragma unroll
        for (int i = 0; i < 16; i++) {
            float4 w = wq4[i];
            a0 = fmaf(s_q[4 * i + 0], w.x, a0);
            a1 = fmaf(s_q[4 * i + 1], w.y, a1);
            a2 = fmaf(s_q[4 * i + 2], w.z, a2);
            a3 = fmaf(s_q[4 * i + 3], w.w, a3);
        }
        s_qb[tid] = (a0 + a1) + (a2 + a3) + bias[tid & (DK - 1)];
    }
    __syncthreads();

    const float bsv = bs[0];

    // ---- scores: thread (h, lg) handles n = lg and n = lg + 64 ----
    #pragma unroll
    for (int p = 0; p < 2; p++) {
        int n = lg + (p << 6);
        if (n < NKEY) {
            // kv row -> registers as packed f32x2
            unsigned long long kv2[DK / 2];
            const ulonglong2* kvr = (const ulonglong2*)(s_kv + n * KVSTR);
            #pragma unroll
            for (int i = 0; i < 16; i++) {
                ulonglong2 v = kvr[i];
                kv2[2 * i]     = v.x;
                kv2[2 * i + 1] = v.y;
            }
            float sA = 0.f, sB = 0.f;
            const float* qbh = s_qb + (h << 6);
            #pragma unroll 4
            for (int k = 0; k < DK; k++) {
                const ulonglong2* w2 =
                    (const ulonglong2*)(s_wk + (((h << 6) + k) << 6));
                unsigned long long a0 = 0ull, a1 = 0ull, a2 = 0ull, a3 = 0ull;
                #pragma unroll
                for (int i = 0; i < 8; i++) {
                    ulonglong2 wa = w2[2 * i];
                    ulonglong2 wb = w2[2 * i + 1];
                    a0 = fma2(kv2[4 * i + 0], wa.x, a0);
                    a1 = fma2(kv2[4 * i + 1], wa.y, a1);
                    a2 = fma2(kv2[4 * i + 2], wb.x, a2);
                    a3 = fma2(kv2[4 * i + 3], wb.y, a3);
                }
                a0 = add2(a0, a1);
                a2 = add2(a2, a3);
                a0 = add2(a0, a2);
                float lo, hi;
                asm("mov.b64 {%0, %1}, %2;" : "=f"(lo), "=f"(hi) : "l"(a0));
                float kk = lo + hi + qbh[k];
                float tv = tanh_fast(kk);
                if (k & 1) sB = fmaf(s_ws[k], tv, sB);
                else       sA = fmaf(s_ws[k], tv, sA);
            }
            s_sc[h * 128 + n] = sA + sB + bsv;
        }
    }
    __syncthreads();

    // ---- softmax over n (127) per head: one warp per head ----
    if (tid < NH * 32) {
        int hh = tid >> 5;
        int ln = tid & 31;
        const float* sc = s_sc + hh * 128;
        float v0 = sc[ln];
        float v1 = sc[ln + 32];
        float v2 = sc[ln + 64];
        float v3 = (ln + 96 < NKEY) ? sc[ln + 96] : -1e30f;
        float m = fmaxf(fmaxf(v0, v1), fmaxf(v2, v3));
        #pragma unroll
        for (int o = 16; o > 0; o >>= 1)
            m = fmaxf(m, __shfl_xor_sync(0xffffffffu, m, o));
        float e0 = __expf(v0 - m);
        float e1 = __expf(v1 - m);
        float e2 = __expf(v2 - m);
        float e3 = (ln + 96 < NKEY) ? __expf(v3 - m) : 0.f;
        float s = (e0 + e1) + (e2 + e3);
        #pragma unroll
        for (int o = 16; o > 0; o >>= 1)
            s += __shfl_xor_sync(0xffffffffu, s, o);
        float inv = 1.f / s;
        float* wr = s_w + hh * 128;
        wr[ln]      = e0 * inv;
        wr[ln + 32] = e1 * inv;
        wr[ln + 64] = e2 * inv;
        if (ln + 96 < NKEY) wr[ln + 96] = e3 * inv;
    }
    __syncthreads();

    // ---- weighted kv sum (values GEMM folded): wv[h][i] = sum_n w[h][n]*kv[n][i]
    {
        const float* wr = s_w + h * 128;
        float a0 = 0.f, a1 = 0.f, a2 = 0.f, a3 = 0.f;
        #pragma unroll 4
        for (int n = 0; n < 124; n += 4) {
            a0 = fmaf(wr[n],     s_kv[n * KVSTR + lg],       a0);
            a1 = fmaf(wr[n + 1], s_kv[(n + 1) * KVSTR + lg], a1);
            a2 = fmaf(wr[n + 2], s_kv[(n + 2) * KVSTR + lg], a2);
            a3 = fmaf(wr[n + 3], s_kv[(n + 3) * KVSTR + lg], a3);
        }
        a0 = fmaf(wr[124], s_kv[124 * KVSTR + lg], a0);
        a1 = fmaf(wr[125], s_kv[125 * KVSTR + lg], a1);
        a2 = fmaf(wr[126], s_kv[126 * KVSTR + lg], a2);
        s_wv[tid] = (a0 + a1) + (a2 + a3);
    }
    __syncthreads();

    // ---- output projection: out[o] = sum_k wv[h][k] * Wv[o][k] ----
    {
        const float* wvh = s_wv + (h << 6);
        const float4* wv4 = (const float4*)(Wv + tid * DK);
        float a0 = 0.f, a1 = 0.f, a2 = 0.f, a3 = 0.f;
        #pragma unroll
        for (int i = 0; i < 16; i++) {
            float4 w = wv4[i];
            a0 = fmaf(wvh[4 * i + 0], w.x, a0);
            a1 = fmaf(wvh[4 * i + 1], w.y, a1);
            a2 = fmaf(wvh[4 * i + 2], w.z, a2);
            a3 = fmaf(wvh[4 * i + 3], w.w, a3);
        }
        out[(size_t)bt * DOUT + tid] = (a0 + a1) + (a2 + a3);
    }
}

extern "C" void kernel_launch(void* const* d_in, const int* in_sizes, int n_in,
                              void* d_out, int out_size) {
    (void)n_in; (void)out_size;
    const float* q_x  = (const float*)d_in[0];
    const float* kv_x = (const float*)d_in[1];
    const float* Wk   = (const float*)d_in[2];
    const float* Wq   = (const float*)d_in[3];
    const float* Wv   = (const float*)d_in[4];
    const float* bias = (const float*)d_in[5];
    const float* Ws   = (const float*)d_in[6];
    const float* bs   = (const float*)d_in[7];
    float* out = (float*)d_out;

    const int BT = in_sizes[0] / DK;  // b*t = 1024

    cudaFuncSetAttribute(raamh_kernel,
                         cudaFuncAttributeMaxDynamicSharedMemorySize,
                         SMEM_BYTES);
    raamh_kernel<<<BT, TPB, SMEM_BYTES>>>(q_x, kv_x, Wk, Wq, Wv,
                                          bias, Ws, bs, out);
}

// round 2
// speedup vs baseline: 1.0523x; 1.0523x over previous
#include <cuda_runtime.h>
#include <cstdint>
#include <cstddef>

#define TPB   256
#define NKEY  127
#define NH    4
#define DK    64
#define DOUT  256
#define STR   68   // padded row stride (floats), 16B-aligned rows, conflict-free

static constexpr int KV_FLOATS = 128 * STR;            // one kv buffer
static constexpr int WK_FLOATS = DOUT * STR;
// layout: kv0 | kv1 | wk | qb[256] | q[64] | ws[64] | bias[64] | sc[512] | w[512] | wv[256] | bs[4]
static constexpr int OFF_KV0  = 0;
static constexpr int OFF_KV1  = OFF_KV0 + KV_FLOATS;
static constexpr int OFF_WK   = OFF_KV1 + KV_FLOATS;
static constexpr int OFF_QB   = OFF_WK + WK_FLOATS;
static constexpr int OFF_Q    = OFF_QB + DOUT;
static constexpr int OFF_WS   = OFF_Q + DK;
static constexpr int OFF_BIAS = OFF_WS + DK;
static constexpr int OFF_SC   = OFF_BIAS + DK;
static constexpr int OFF_W    = OFF_SC + NH * 128;
static constexpr int OFF_WV   = OFF_W + NH * 128;
static constexpr int OFF_BS   = OFF_WV + DOUT;
static constexpr int SMEM_FLOATS = OFF_BS + 4;
static constexpr int SMEM_BYTES  = SMEM_FLOATS * 4;

__device__ __forceinline__ float tanh_fast(float x) {
    float y;
    asm("tanh.approx.f32 %0, %1;" : "=f"(y) : "f"(x));
    return y;
}
__device__ __forceinline__ unsigned long long fma2(unsigned long long a,
                                                   unsigned long long b,
                                                   unsigned long long c) {
    unsigned long long d;
    asm("fma.rn.f32x2 %0, %1, %2, %3;" : "=l"(d) : "l"(a), "l"(b), "l"(c));
    return d;
}

#define CP_ASYNC16(sdst, gsrc)                                                \
    asm volatile("cp.async.cg.shared.global [%0], [%1], 16;"                  \
                 :: "r"(sdst), "l"(gsrc))
#define CP_COMMIT() asm volatile("cp.async.commit_group;")
#define CP_WAIT1()  asm volatile("cp.async.wait_group 1;")

__device__ __forceinline__ void prefetch_kv(const float* __restrict__ gsrc,
                                            float* sdst) {
    // 127 rows x 64 floats, contiguous in gmem, stride-68 rows in smem
    #pragma unroll 2
    for (int j = threadIdx.x; j < NKEY * 16; j += TPB) {
        int row = j >> 4;
        int c4  = j & 15;
        unsigned sa =
            (unsigned)__cvta_generic_to_shared(sdst + row * STR + c4 * 4);
        CP_ASYNC16(sa, gsrc + j * 4);
    }
}

__global__ void __launch_bounds__(TPB, 1)
raamh_kernel(const float* __restrict__ q_x, const float* __restrict__ kv_x,
             const float* __restrict__ Wk,  const float* __restrict__ Wq,
             const float* __restrict__ Wv,  const float* __restrict__ bias,
             const float* __restrict__ Ws,  const float* __restrict__ bs,
             float* __restrict__ out, int BT)
{
    extern __shared__ float smem[];
    float* s_kv[2] = { smem + OFF_KV0, smem + OFF_KV1 };
    float* s_wk   = smem + OFF_WK;
    float* s_qb   = smem + OFF_QB;
    float* s_q    = smem + OFF_Q;
    float* s_ws   = smem + OFF_WS;
    float* s_bias = smem + OFF_BIAS;
    float* s_sc   = smem + OFF_SC;
    float* s_w    = smem + OFF_W;
    float* s_wv   = smem + OFF_WV;
    float* s_bs   = smem + OFF_BS;

    const int tid  = threadIdx.x;
    const int lane = tid & 31;
    const int wrp  = tid >> 5;
    const int ng   = lane & 3;
    const int og   = lane >> 2;
    const int h    = tid >> 6;     // head for weighted-sum / out-proj phases
    const int lg   = tid & 63;

    // ---- one-time staging: Wk (stride-68), Ws, bias, bs ----
    {
        const float4* wk4 = (const float4*)Wk;
        #pragma unroll 4
        for (int j = tid; j < DOUT * 16; j += TPB) {
            int row = j >> 4, c4 = j & 15;
            float4 v = wk4[j];
            *(float4*)(s_wk + row * STR + c4 * 4) = v;
        }
        if (tid < DK) {
            s_ws[tid]   = Ws[tid];
            s_bias[tid] = bias[tid];
        }
        if (tid == 0) s_bs[0] = bs[0];
    }

    // ---- prologue prefetch of first kv tile ----
    int bt0 = blockIdx.x;
    int buf = 0;
    prefetch_kv(kv_x + (size_t)bt0 * (NKEY * DK), s_kv[0]);
    CP_COMMIT();

    for (int bt = bt0; bt < BT; bt += gridDim.x) {
        // stage q for this tile (independent of cp.async)
        if (tid < DK) s_q[tid] = q_x[bt * DK + tid];

        // prefetch next kv tile into the other buffer
        int bt_next = bt + gridDim.x;
        if (bt_next < BT)
            prefetch_kv(kv_x + (size_t)bt_next * (NKEY * DK), s_kv[buf ^ 1]);
        CP_COMMIT();
        CP_WAIT1();            // current tile's group is now complete
        __syncthreads();

        const float* kvb = s_kv[buf];

        // ---- q projection + bias: qb[o] = q . Wq[o] + bias[o&63] ----
        {
            const float4* wq4 = (const float4*)(Wq + tid * DK);
            float a0 = 0.f, a1 = 0.f, a2 = 0.f, a3 = 0.f;
            #pragma unroll
            for (int i = 0; i < 16; i++) {
                float4 w = __ldg(wq4 + i);
                a0 = fmaf(s_q[4 * i + 0], w.x, a0);
                a1 = fmaf(s_q[4 * i + 1], w.y, a1);
                a2 = fmaf(s_q[4 * i + 2], w.z, a2);
                a3 = fmaf(s_q[4 * i + 3], w.w, a3);
            }
            s_qb[tid] = (a0 + a1) + (a2 + a3) + s_bias[tid & (DK - 1)];
        }
        __syncthreads();

        const float bsv = s_bs[0];

        // ---- score GEMM, register-tiled 4n x 8o per thread ----
        // warp covers 16 n (4 ng-lanes x 4 j, interleaved mod 4)
        // and one head's 64 o (8 og-lanes x 8 oi, interleaved mod 8)
        #pragma unroll 1
        for (int it = 0; it < 4; ++it) {
            const int task = wrp * 4 + it;        // 0..31
            const int head = task & 3;
            const int nb   = task >> 2;           // 0..7, 16 n each
            const float* kvp = kvb  + (nb * 16 + ng) * STR;
            const float* wkp = s_wk + (head * 64 + og) * STR;

            unsigned long long acc[4][8];
            #pragma unroll
            for (int j = 0; j < 4; ++j)
                #pragma unroll
                for (int oi = 0; oi < 8; ++oi) acc[j][oi] = 0ull;

            #pragma unroll 4
            for (int kk = 0; kk < DK; kk += 4) {
                ulonglong2 kvv[4];
                #pragma unroll
                for (int j = 0; j < 4; ++j)
                    kvv[j] = *(const ulonglong2*)(kvp + j * 4 * STR + kk);
                #pragma unroll
                for (int oi = 0; oi < 8; ++oi) {
                    ulonglong2 wkv =
                        *(const ulonglong2*)(wkp + oi * 8 * STR + kk);
                    #pragma unroll
                    for (int j = 0; j < 4; ++j) {
                        acc[j][oi] = fma2(kvv[j].x, wkv.x, acc[j][oi]);
                        acc[j][oi] = fma2(kvv[j].y, wkv.y, acc[j][oi]);
                    }
                }
            }

            // epilogue: tanh + Ws-weighted reduction over this thread's 8 o
            float part[4] = {0.f, 0.f, 0.f, 0.f};
            #pragma unroll
            for (int oi = 0; oi < 8; ++oi) {
                int k = oi * 8 + og;
                float wsk = s_ws[k];
                float qbo = s_qb[head * 64 + k];
                #pragma unroll
                for (int j = 0; j < 4; ++j) {
                    float lo, hi;
                    asm("mov.b64 {%0, %1}, %2;"
                        : "=f"(lo), "=f"(hi) : "l"(acc[j][oi]));
                    part[j] = fmaf(wsk, tanh_fast(lo + hi + qbo), part[j]);
                }
            }
            // reduce over og lanes (lane bits 2..4)
            #pragma unroll
            for (int m = 4; m <= 16; m <<= 1)
                #pragma unroll
                for (int j = 0; j < 4; ++j)
                    part[j] += __shfl_xor_sync(0xffffffffu, part[j], m);
            if (og == 0) {
                #pragma unroll
                for (int j = 0; j < 4; ++j)
                    s_sc[head * 128 + nb * 16 + j * 4 + ng] = part[j] + bsv;
            }
        }
        __syncthreads();

        // ---- softmax over n (127) per head: one warp per head ----
        if (tid < NH * 32) {
            int hh = tid >> 5;
            int ln = tid & 31;
            const float* sc = s_sc + hh * 128;
            float v0 = sc[ln];
            float v1 = sc[ln + 32];
            float v2 = sc[ln + 64];
            float v3 = (ln + 96 < NKEY) ? sc[ln + 96] : -1e30f;
            float m = fmaxf(fmaxf(v0, v1), fmaxf(v2, v3));
            #pragma unroll
            for (int o = 16; o > 0; o >>= 1)
                m = fmaxf(m, __shfl_xor_sync(0xffffffffu, m, o));
            float e0 = __expf(v0 - m);
            float e1 = __expf(v1 - m);
            float e2 = __expf(v2 - m);
            float e3 = (ln + 96 < NKEY) ? __expf(v3 - m) : 0.f;
            float s = (e0 + e1) + (e2 + e3);
            #pragma unroll
            for (int o = 16; o > 0; o >>= 1)
                s += __shfl_xor_sync(0xffffffffu, s, o);
            float inv = 1.f / s;
            float* wr = s_w + hh * 128;
            wr[ln]      = e0 * inv;
            wr[ln + 32] = e1 * inv;
            wr[ln + 64] = e2 * inv;
            if (ln + 96 < NKEY) wr[ln + 96] = e3 * inv;
        }
        __syncthreads();

        // ---- weighted kv sum: wv[h][i] = sum_n w[h][n] * kv[n][i] ----
        {
            const float* wr = s_w + h * 128;
            float a0 = 0.f, a1 = 0.f, a2 = 0.f, a3 = 0.f;
            #pragma unroll 4
            for (int n = 0; n < 124; n += 4) {
                a0 = fmaf(wr[n],     kvb[n * STR + lg],       a0);
                a1 = fmaf(wr[n + 1], kvb[(n + 1) * STR + lg], a1);
                a2 = fmaf(wr[n + 2], kvb[(n + 2) * STR + lg], a2);
                a3 = fmaf(wr[n + 3], kvb[(n + 3) * STR + lg], a3);
            }
            a0 = fmaf(wr[124], kvb[124 * STR + lg], a0);
            a1 = fmaf(wr[125], kvb[125 * STR + lg], a1);
            a2 = fmaf(wr[126], kvb[126 * STR + lg], a2);
            s_wv[tid] = (a0 + a1) + (a2 + a3);
        }
        __syncthreads();   // also guards kv buffer reuse by next prefetch

        // ---- output projection: out[o] = sum_k wv[h][k] * Wv[o][k] ----
        {
            const float* wvh = s_wv + (h << 6);
            const float4* wv4 = (const float4*)(Wv + tid * DK);
            float a0 = 0.f, a1 = 0.f, a2 = 0.f, a3 = 0.f;
            #pragma unroll
            for (int i = 0; i < 16; i++) {
                float4 w = __ldg(wv4 + i);
                a0 = fmaf(wvh[4 * i + 0], w.x, a0);
                a1 = fmaf(wvh[4 * i + 1], w.y, a1);
                a2 = fmaf(wvh[4 * i + 2], w.z, a2);
                a3 = fmaf(wvh[4 * i + 3], w.w, a3);
            }
            out[(size_t)bt * DOUT + tid] = (a0 + a1) + (a2 + a3);
        }

        buf ^= 1;
    }
}

extern "C" void kernel_launch(void* const* d_in, const int* in_sizes, int n_in,
                              void* d_out, int out_size) {
    (void)n_in; (void)out_size;
    const float* q_x  = (const float*)d_in[0];
    const float* kv_x = (const float*)d_in[1];
    const float* Wk   = (const float*)d_in[2];
    const float* Wq   = (const float*)d_in[3];
    const float* Wv   = (const float*)d_in[4];
    const float* bias = (const float*)d_in[5];
    const float* Ws   = (const float*)d_in[6];
    const float* bs   = (const float*)d_in[7];
    float* out = (float*)d_out;

    const int BT = in_sizes[0] / DK;          // b*t
    int grid = BT < 152 ? BT : 152;           // persistent: 1 block/SM

    cudaFuncSetAttribute(raamh_kernel,
                         cudaFuncAttributeMaxDynamicSharedMemorySize,
                         SMEM_BYTES);
    raamh_kernel<<<grid, TPB, SMEM_BYTES>>>(q_x, kv_x, Wk, Wq, Wv,
                                            bias, Ws, bs, out, BT);
}